// round 3
// baseline (speedup 1.0000x reference)
#include <cuda_runtime.h>
#include <cuda_bf16.h>
#include <cstddef>

#define NN 10000
#define NE 320000
#define DD 256

// ---------------- scratch (device globals; no runtime allocation) ----------
__device__ float g_T[2 * NN * DD];      // edge-NN layer-1 output, per relation
__device__ float g_H[2 * NN * DD];      // edge-NN layer-2 output, per relation
__device__ float g_agg[NN * DD];        // scatter-sum result
__device__ float g_gates[NN * 4 * DD];  // LSTM gates
__device__ float g_hn[NN * DD];         // LSTM output
__device__ float g_x1[NN * 128];
__device__ float g_x2[NN * 128];
__device__ float g_bcomb[4 * DD];       // b_ih + b_hh

// ---------------- generic fused GEMM: C = act(A @ W^T + bias) --------------
// A: [M,K] row-major, W: [N,K] row-major, bias: [N], C: [M,N]
// 128x128 block tile, BK=16, 256 threads, 8x8 per-thread tile.
// blockIdx.z batches independent problems via the s* strides.
// Requires: N % 128 == 0, K % 16 == 0. M is guarded.
template <int ACT>
__global__ void __launch_bounds__(256)
gemm_bias(const float* __restrict__ A, const float* __restrict__ W,
          const float* __restrict__ bias, float* __restrict__ C,
          int M, int N, int K,
          long sA, long sW, long sB, long sC)
{
    A    += (long)blockIdx.z * sA;
    W    += (long)blockIdx.z * sW;
    bias += (long)blockIdx.z * sB;
    C    += (long)blockIdx.z * sC;

    const int tx = threadIdx.x, ty = threadIdx.y;
    const int tid = ty * 16 + tx;
    const int lr = tid >> 2;          // 0..63
    const int lc = (tid & 3) << 2;    // 0,4,8,12
    const int m0 = blockIdx.y * 128;
    const int n0 = blockIdx.x * 128;

    __shared__ float As[16][132];     // [k][m], pad 4 floats (keeps 16B align)
    __shared__ float Bs[16][132];     // [k][n]

    float acc[8][8];
#pragma unroll
    for (int i = 0; i < 8; i++)
#pragma unroll
        for (int j = 0; j < 8; j++) acc[i][j] = 0.f;

    for (int k0 = 0; k0 < K; k0 += 16) {
#pragma unroll
        for (int h = 0; h < 2; h++) {
            int m = lr + h * 64;
            int gm = m0 + m;
            float4 v = make_float4(0.f, 0.f, 0.f, 0.f);
            if (gm < M) v = *(const float4*)(A + (size_t)gm * K + k0 + lc);
            As[lc + 0][m] = v.x; As[lc + 1][m] = v.y;
            As[lc + 2][m] = v.z; As[lc + 3][m] = v.w;

            int n = lr + h * 64;
            float4 w = *(const float4*)(W + (size_t)(n0 + n) * K + k0 + lc);
            Bs[lc + 0][n] = w.x; Bs[lc + 1][n] = w.y;
            Bs[lc + 2][n] = w.z; Bs[lc + 3][n] = w.w;
        }
        __syncthreads();
#pragma unroll
        for (int k = 0; k < 16; k++) {
            float a[8], b[8];
            *(float4*)&a[0] = *(const float4*)&As[k][ty * 4];
            *(float4*)&a[4] = *(const float4*)&As[k][ty * 4 + 64];
            *(float4*)&b[0] = *(const float4*)&Bs[k][tx * 4];
            *(float4*)&b[4] = *(const float4*)&Bs[k][tx * 4 + 64];
#pragma unroll
            for (int i = 0; i < 8; i++)
#pragma unroll
                for (int j = 0; j < 8; j++)
                    acc[i][j] = fmaf(a[i], b[j], acc[i][j]);
        }
        __syncthreads();
    }

#pragma unroll
    for (int ih = 0; ih < 2; ih++) {
#pragma unroll
        for (int i = 0; i < 4; i++) {
            int m = m0 + ty * 4 + ih * 64 + i;
            if (m >= M) continue;
#pragma unroll
            for (int jh = 0; jh < 2; jh++) {
                int n = n0 + tx * 4 + jh * 64;
                float4 bv = *(const float4*)(bias + n);
                float4 o;
                o.x = acc[ih * 4 + i][jh * 4 + 0] + bv.x;
                o.y = acc[ih * 4 + i][jh * 4 + 1] + bv.y;
                o.z = acc[ih * 4 + i][jh * 4 + 2] + bv.z;
                o.w = acc[ih * 4 + i][jh * 4 + 3] + bv.w;
                if (ACT) {
                    o.x = fmaxf(o.x, 0.f); o.y = fmaxf(o.y, 0.f);
                    o.z = fmaxf(o.z, 0.f); o.w = fmaxf(o.w, 0.f);
                }
                *(float4*)(C + (size_t)m * N + n) = o;
            }
        }
    }
}

// ---------------- small helpers --------------------------------------------
__global__ void zero_kernel(float4* __restrict__ p, int n4)
{
    int i = blockIdx.x * blockDim.x + threadIdx.x;
    if (i < n4) p[i] = make_float4(0.f, 0.f, 0.f, 0.f);
}

__global__ void bcomb_kernel(const float* __restrict__ a,
                             const float* __restrict__ b,
                             float* __restrict__ c)
{
    int i = threadIdx.x;  // 1024 threads
    c[i] = a[i] + b[i];
}

// ---------------- scatter: agg[dst[e]] += H[rel[e]][src[e]] ----------------
// One warp per edge; vector (16B) global reductions cut atomic op count 4x.
__global__ void __launch_bounds__(256)
scatter_kernel(const float* __restrict__ H, const int* __restrict__ src,
               const int* __restrict__ dst, const int* __restrict__ rel,
               float* __restrict__ agg)
{
    int e = blockIdx.x * 8 + (threadIdx.x >> 5);
    if (e >= NE) return;
    int lane = threadIdx.x & 31;
    int s = src[e], d = dst[e], r = rel[e];
    const float4* hrow = (const float4*)(H + ((size_t)r * NN + s) * DD);
    float* arow = agg + (size_t)d * DD;
#pragma unroll
    for (int t = 0; t < 2; t++) {
        int idx = lane + t * 32;
        float4 v = __ldg(&hrow[idx]);
        asm volatile("red.global.add.v4.f32 [%0], {%1, %2, %3, %4};"
                     :: "l"(arow + idx * 4),
                        "f"(v.x), "f"(v.y), "f"(v.z), "f"(v.w)
                     : "memory");
    }
}

// ---------------- LSTM elementwise (c0 = h0 = 0, so f-gate is dead) --------
__global__ void lstm_kernel(const float* __restrict__ gates,
                            float* __restrict__ hn)
{
    int i = blockIdx.x * blockDim.x + threadIdx.x;
    if (i >= NN * DD) return;
    int n = i >> 8;          // / 256
    int c = i & 255;
    const float* gr = gates + (size_t)n * (4 * DD);
    float ig = gr[c];
    float gg = gr[2 * DD + c];
    float og = gr[3 * DD + c];
    float si = 1.f / (1.f + expf(-ig));
    float cc = si * tanhf(gg);
    float so = 1.f / (1.f + expf(-og));
    hn[i] = so * tanhf(cc);
}

// ---------------- launcher --------------------------------------------------
extern "C" void kernel_launch(void* const* d_in, const int* in_sizes, int n_in,
                              void* d_out, int out_size)
{
    const float* feat  = (const float*)d_in[0];
    const int*   src   = (const int*)d_in[1];
    const int*   dst   = (const int*)d_in[2];
    const int*   rel   = (const int*)d_in[3];
    const float* W_rel = (const float*)d_in[4];
    const float* b_rel = (const float*)d_in[5];
    const float* W_ih  = (const float*)d_in[6];
    const float* b_ih  = (const float*)d_in[7];
    const float* b_hh  = (const float*)d_in[8];
    const float* W1    = (const float*)d_in[9];
    const float* b1    = (const float*)d_in[10];
    const float* W2    = (const float*)d_in[11];
    const float* b2    = (const float*)d_in[12];
    const float* W3    = (const float*)d_in[13];
    const float* b3    = (const float*)d_in[14];
    float* out = (float*)d_out;

    float *T, *H, *agg, *gates, *hn, *x1, *x2, *bc;
    cudaGetSymbolAddress((void**)&T,     g_T);
    cudaGetSymbolAddress((void**)&H,     g_H);
    cudaGetSymbolAddress((void**)&agg,   g_agg);
    cudaGetSymbolAddress((void**)&gates, g_gates);
    cudaGetSymbolAddress((void**)&hn,    g_hn);
    cudaGetSymbolAddress((void**)&x1,    g_x1);
    cudaGetSymbolAddress((void**)&x2,    g_x2);
    cudaGetSymbolAddress((void**)&bc,    g_bcomb);

    dim3 blk(16, 16);
    const int MB = (NN + 127) / 128;  // 79 row tiles
    const long ND = (long)NN * DD;

    // independent prep work first
    zero_kernel<<<(NN * DD / 4 + 255) / 256, 256>>>((float4*)agg, NN * DD / 4);
    bcomb_kernel<<<1, 1024>>>(b_ih, b_hh, bc);

    // edge-NN, deduped to per-(node, relation): layer 1 then layer 2,
    // both relations batched via blockIdx.z
    gemm_bias<1><<<dim3(DD / 128, MB, 2), blk>>>(
        feat, W_rel, b_rel, T, NN, DD, DD,
        0L, (long)DD * DD, (long)DD, ND);
    gemm_bias<1><<<dim3(DD / 128, MB, 2), blk>>>(
        T, W_rel, b_rel, H, NN, DD, DD,
        ND, (long)DD * DD, (long)DD, ND);

    // scatter-sum into destination nodes
    scatter_kernel<<<NE / 8, 256>>>(H, src, dst, rel, agg);

    // LSTM gates GEMM (+ combined bias), then elementwise LSTM
    gemm_bias<0><<<dim3(4 * DD / 128, MB, 1), blk>>>(
        agg, W_ih, bc, gates, NN, 4 * DD, DD, 0L, 0L, 0L, 0L);
    lstm_kernel<<<(NN * DD + 255) / 256, 256>>>(gates, hn);

    // global-update MLP
    gemm_bias<1><<<dim3(1, MB, 1), blk>>>(hn, W1, b1, x1, NN, 128, DD,
                                          0L, 0L, 0L, 0L);
    gemm_bias<1><<<dim3(1, MB, 1), blk>>>(x1, W2, b2, x2, NN, 128, 128,
                                          0L, 0L, 0L, 0L);
    gemm_bias<0><<<dim3(DD / 128, MB, 1), blk>>>(x2, W3, b3, out, NN, DD, 128,
                                                 0L, 0L, 0L, 0L);
}

// round 7
// speedup vs baseline: 1.2311x; 1.2311x over previous
#include <cuda_runtime.h>
#include <cuda_bf16.h>
#include <cstddef>
#include <cstdint>

#define NN 10000
#define NE 320000
#define DD 256

// ---------------- scratch (device globals; no runtime allocation) ----------
__device__ float g_T[2 * NN * DD];      // edge-NN layer-1 output, per relation
__device__ float g_H[2 * NN * DD];      // edge-NN layer-2 output, per relation
__device__ float g_agg[NN * DD];        // scatter-sum result
__device__ float g_gates[NN * 4 * DD];  // LSTM gates (f columns unwritten)
__device__ float g_hn[NN * DD];         // LSTM output
__device__ float g_x1[NN * 128];
__device__ float g_x2[NN * 128];
__device__ float g_bcomb[4 * DD];       // b_ih + b_hh

// ---------------- tf32 helpers ---------------------------------------------
__device__ __forceinline__ float tf32r(float x)
{
    uint32_t u;
    asm("cvt.rna.tf32.f32 %0, %1;" : "=r"(u) : "f"(x));
    return __uint_as_float(u);
}

__device__ __forceinline__ void mma8(float* c, const uint32_t* a, const uint32_t* b)
{
    asm volatile(
        "mma.sync.aligned.m16n8k8.row.col.f32.tf32.tf32.f32 "
        "{%0,%1,%2,%3}, {%4,%5,%6,%7}, {%8,%9}, {%0,%1,%2,%3};"
        : "+f"(c[0]), "+f"(c[1]), "+f"(c[2]), "+f"(c[3])
        : "r"(a[0]), "r"(a[1]), "r"(a[2]), "r"(a[3]), "r"(b[0]), "r"(b[1]));
}

#define PITCH 36
#define TILE_F (128 * PITCH)
#define SMEM_BYTES (4 * TILE_F * 4)

// --------- 3xTF32 tensor-core GEMM: C = act(A @ W^T + bias) ----------------
// Error-compensated tf32 (a_hi*b_hi + a_hi*b_lo + a_lo*b_hi): ~fp32 accuracy.
// A: [M,K] rm, W: [N,K] rm, bias: [N], C: [M,N] rm.
// 128x128 block tile, BK=32, 256 threads = 8 warps (2m x 4n), warp 64x32.
// blockIdx.z batches via strides. N%128==0, K%32==0; M guarded.
// SKIPF: remap column tiles 2..5 -> +256 (skip dead LSTM f-gate columns).
template <int ACT, int SKIPF>
__global__ void __launch_bounds__(256)
tgemm(const float* __restrict__ A, const float* __restrict__ W,
      const float* __restrict__ bias, float* __restrict__ C,
      int M, int N, int K,
      long sA, long sW, long sB, long sC)
{
    A    += (long)blockIdx.z * sA;
    W    += (long)blockIdx.z * sW;
    bias += (long)blockIdx.z * sB;
    C    += (long)blockIdx.z * sC;

    extern __shared__ float sm[];
    float* Ah = sm;                 // [128][36] hi
    float* Al = Ah + TILE_F;        // [128][36] lo
    float* Wh = Al + TILE_F;
    float* Wl = Wh + TILE_F;

    const int tid  = threadIdx.x;
    const int lane = tid & 31;
    const int wid  = tid >> 5;
    const int wm   = (wid & 1) * 64;
    const int wn   = (wid >> 1) * 32;

    const int m0 = blockIdx.y * 128;
    int n0 = blockIdx.x * 128;
    if (SKIPF && blockIdx.x >= 2) n0 += 256;

    const int lrow = tid >> 3;        // 0..31
    const int lcol = (tid & 7) * 4;   // 0..28

    float4 ra[4], rw[4];
#pragma unroll
    for (int i = 0; i < 4; i++) {
        int r  = lrow + i * 32;
        int gm = m0 + r;
        ra[i] = (gm < M) ? *(const float4*)(A + (size_t)gm * K + lcol)
                         : make_float4(0.f, 0.f, 0.f, 0.f);
        rw[i] = *(const float4*)(W + (size_t)(n0 + r) * K + lcol);
    }

    float acc[4][4][4];
#pragma unroll
    for (int mi = 0; mi < 4; mi++)
#pragma unroll
        for (int ni = 0; ni < 4; ni++)
#pragma unroll
            for (int q = 0; q < 4; q++) acc[mi][ni][q] = 0.f;

    for (int k0 = 0; k0 < K; k0 += 32) {
        // regs -> smem, hi/lo split (lo = exact residual, representable)
#pragma unroll
        for (int i = 0; i < 4; i++) {
            int off = (lrow + i * 32) * PITCH + lcol;
            float4 v = ra[i], h, l;
            h.x = tf32r(v.x); l.x = tf32r(v.x - h.x);
            h.y = tf32r(v.y); l.y = tf32r(v.y - h.y);
            h.z = tf32r(v.z); l.z = tf32r(v.z - h.z);
            h.w = tf32r(v.w); l.w = tf32r(v.w - h.w);
            *(float4*)&Ah[off] = h;
            *(float4*)&Al[off] = l;
            v = rw[i];
            h.x = tf32r(v.x); l.x = tf32r(v.x - h.x);
            h.y = tf32r(v.y); l.y = tf32r(v.y - h.y);
            h.z = tf32r(v.z); l.z = tf32r(v.z - h.z);
            h.w = tf32r(v.w); l.w = tf32r(v.w - h.w);
            *(float4*)&Wh[off] = h;
            *(float4*)&Wl[off] = l;
        }
        __syncthreads();

        // prefetch next k-slice
        int k1 = k0 + 32;
        if (k1 < K) {
#pragma unroll
            for (int i = 0; i < 4; i++) {
                int r  = lrow + i * 32;
                int gm = m0 + r;
                ra[i] = (gm < M) ? *(const float4*)(A + (size_t)gm * K + k1 + lcol)
                                 : make_float4(0.f, 0.f, 0.f, 0.f);
                rw[i] = *(const float4*)(W + (size_t)(n0 + r) * K + k1 + lcol);
            }
        }

#pragma unroll
        for (int kk = 0; kk < 4; kk++) {
            const int kb = kk * 8;
            uint32_t ah[4][4], al[4][4], bh[4][2], bl[4][2];
#pragma unroll
            for (int mi = 0; mi < 4; mi++) {
                int r = wm + mi * 16 + (lane >> 2);
                int c = kb + (lane & 3);
                int o0 = r * PITCH + c;
                int o1 = (r + 8) * PITCH + c;
                ah[mi][0] = __float_as_uint(Ah[o0]);
                ah[mi][1] = __float_as_uint(Ah[o1]);
                ah[mi][2] = __float_as_uint(Ah[o0 + 4]);
                ah[mi][3] = __float_as_uint(Ah[o1 + 4]);
                al[mi][0] = __float_as_uint(Al[o0]);
                al[mi][1] = __float_as_uint(Al[o1]);
                al[mi][2] = __float_as_uint(Al[o0 + 4]);
                al[mi][3] = __float_as_uint(Al[o1 + 4]);
            }
#pragma unroll
            for (int ni = 0; ni < 4; ni++) {
                int r = wn + ni * 8 + (lane >> 2);
                int c = kb + (lane & 3);
                int o = r * PITCH + c;
                bh[ni][0] = __float_as_uint(Wh[o]);
                bh[ni][1] = __float_as_uint(Wh[o + 4]);
                bl[ni][0] = __float_as_uint(Wl[o]);
                bl[ni][1] = __float_as_uint(Wl[o + 4]);
            }
#pragma unroll
            for (int mi = 0; mi < 4; mi++)
#pragma unroll
                for (int ni = 0; ni < 4; ni++) {
                    mma8(acc[mi][ni], ah[mi], bh[ni]);
                    mma8(acc[mi][ni], ah[mi], bl[ni]);
                    mma8(acc[mi][ni], al[mi], bh[ni]);
                }
        }
        __syncthreads();
    }

    // epilogue: bias + activation, float2 stores
#pragma unroll
    for (int mi = 0; mi < 4; mi++) {
        int row = m0 + wm + mi * 16 + (lane >> 2);
#pragma unroll
        for (int ni = 0; ni < 4; ni++) {
            int col = n0 + wn + ni * 8 + (lane & 3) * 2;
            float2 bv = *(const float2*)(bias + col);
            float2 o0, o1;
            o0.x = acc[mi][ni][0] + bv.x;
            o0.y = acc[mi][ni][1] + bv.y;
            o1.x = acc[mi][ni][2] + bv.x;
            o1.y = acc[mi][ni][3] + bv.y;
            if (ACT) {
                o0.x = fmaxf(o0.x, 0.f); o0.y = fmaxf(o0.y, 0.f);
                o1.x = fmaxf(o1.x, 0.f); o1.y = fmaxf(o1.y, 0.f);
            }
            if (row < M)     *(float2*)(C + (size_t)row * N + col)       = o0;
            if (row + 8 < M) *(float2*)(C + (size_t)(row + 8) * N + col) = o1;
        }
    }
}

// ---------------- small helpers --------------------------------------------
__global__ void zero_kernel(float4* __restrict__ p, int n4)
{
    int i = blockIdx.x * blockDim.x + threadIdx.x;
    if (i < n4) p[i] = make_float4(0.f, 0.f, 0.f, 0.f);
}

__global__ void bcomb_kernel(const float* __restrict__ a,
                             const float* __restrict__ b,
                             float* __restrict__ c)
{
    int i = threadIdx.x;  // 1024 threads
    c[i] = a[i] + b[i];
}

// ---------------- scatter: agg[dst[e]] += H[rel[e]][src[e]] ----------------
__global__ void __launch_bounds__(256)
scatter_kernel(const float* __restrict__ H, const int* __restrict__ src,
               const int* __restrict__ dst, const int* __restrict__ rel,
               float* __restrict__ agg)
{
    int e = blockIdx.x * 8 + (threadIdx.x >> 5);
    if (e >= NE) return;
    int lane = threadIdx.x & 31;
    int s = src[e], d = dst[e], r = rel[e];
    const float4* hrow = (const float4*)(H + ((size_t)r * NN + s) * DD);
    float* arow = agg + (size_t)d * DD;
#pragma unroll
    for (int t = 0; t < 2; t++) {
        int idx = lane + t * 32;
        float4 v = __ldg(&hrow[idx]);
        asm volatile("red.global.add.v4.f32 [%0], {%1, %2, %3, %4};"
                     :: "l"(arow + idx * 4),
                        "f"(v.x), "f"(v.y), "f"(v.z), "f"(v.w)
                     : "memory");
    }
}

// ---------------- LSTM elementwise (c0 = h0 = 0, f-gate dead) --------------
__global__ void lstm_kernel(const float* __restrict__ gates,
                            float* __restrict__ hn)
{
    int i = blockIdx.x * blockDim.x + threadIdx.x;
    if (i >= NN * DD) return;
    int n = i >> 8;
    int c = i & 255;
    const float* gr = gates + (size_t)n * (4 * DD);
    float ig = gr[c];
    float gg = gr[2 * DD + c];
    float og = gr[3 * DD + c];
    float si = 1.f / (1.f + expf(-ig));
    float cc = si * tanhf(gg);
    float so = 1.f / (1.f + expf(-og));
    hn[i] = so * tanhf(cc);
}

// ---------------- launcher --------------------------------------------------
extern "C" void kernel_launch(void* const* d_in, const int* in_sizes, int n_in,
                              void* d_out, int out_size)
{
    const float* feat  = (const float*)d_in[0];
    const int*   src   = (const int*)d_in[1];
    const int*   dst   = (const int*)d_in[2];
    const int*   rel   = (const int*)d_in[3];
    const float* W_rel = (const float*)d_in[4];
    const float* b_rel = (const float*)d_in[5];
    const float* W_ih  = (const float*)d_in[6];
    const float* b_ih  = (const float*)d_in[7];
    const float* b_hh  = (const float*)d_in[8];
    const float* W1    = (const float*)d_in[9];
    const float* b1    = (const float*)d_in[10];
    const float* W2    = (const float*)d_in[11];
    const float* b2    = (const float*)d_in[12];
    const float* W3    = (const float*)d_in[13];
    const float* b3    = (const float*)d_in[14];
    float* out = (float*)d_out;

    float *T, *H, *agg, *gates, *hn, *x1, *x2, *bc;
    cudaGetSymbolAddress((void**)&T,     g_T);
    cudaGetSymbolAddress((void**)&H,     g_H);
    cudaGetSymbolAddress((void**)&agg,   g_agg);
    cudaGetSymbolAddress((void**)&gates, g_gates);
    cudaGetSymbolAddress((void**)&hn,    g_hn);
    cudaGetSymbolAddress((void**)&x1,    g_x1);
    cudaGetSymbolAddress((void**)&x2,    g_x2);
    cudaGetSymbolAddress((void**)&bc,    g_bcomb);

    // allow 72KB dynamic smem (host-side state set; no stream work enqueued)
    cudaFuncSetAttribute(tgemm<1, 0>,
        cudaFuncAttributeMaxDynamicSharedMemorySize, SMEM_BYTES);
    cudaFuncSetAttribute(tgemm<0, 1>,
        cudaFuncAttributeMaxDynamicSharedMemorySize, SMEM_BYTES);
    cudaFuncSetAttribute(tgemm<0, 0>,
        cudaFuncAttributeMaxDynamicSharedMemorySize, SMEM_BYTES);

    const int MB = (NN + 127) / 128;  // 79 row tiles
    const long ND = (long)NN * DD;

    // independent prep work first
    zero_kernel<<<(NN * DD / 4 + 255) / 256, 256>>>((float4*)agg, NN * DD / 4);
    bcomb_kernel<<<1, 1024>>>(b_ih, b_hh, bc);

    // edge-NN deduped to per-(node, relation), both relations via blockIdx.z
    tgemm<1, 0><<<dim3(DD / 128, MB, 2), 256, SMEM_BYTES>>>(
        feat, W_rel, b_rel, T, NN, DD, DD,
        0L, (long)DD * DD, (long)DD, ND);
    tgemm<1, 0><<<dim3(DD / 128, MB, 2), 256, SMEM_BYTES>>>(
        T, W_rel, b_rel, H, NN, DD, DD,
        ND, (long)DD * DD, (long)DD, ND);

    // scatter-sum into destination nodes
    scatter_kernel<<<NE / 8, 256>>>(H, src, dst, rel, agg);

    // LSTM gates GEMM: only i,g,o gate columns (f-gate dead, grid.x=6 remapped)
    tgemm<0, 1><<<dim3(6, MB, 1), 256, SMEM_BYTES>>>(
        agg, W_ih, bc, gates, NN, 4 * DD, DD, 0L, 0L, 0L, 0L);
    lstm_kernel<<<(NN * DD + 255) / 256, 256>>>(gates, hn);

    // global-update MLP
    tgemm<1, 0><<<dim3(1, MB, 1), 256, SMEM_BYTES>>>(hn, W1, b1, x1, NN, 128, DD,
                                                     0L, 0L, 0L, 0L);
    tgemm<1, 0><<<dim3(1, MB, 1), 256, SMEM_BYTES>>>(x1, W2, b2, x2, NN, 128, 128,
                                                     0L, 0L, 0L, 0L);
    tgemm<0, 0><<<dim3(DD / 128, MB, 1), 256, SMEM_BYTES>>>(x2, W3, b3, out,
                                                            NN, DD, 128,
                                                            0L, 0L, 0L, 0L);
}

// round 8
// speedup vs baseline: 1.2615x; 1.0247x over previous
#include <cuda_runtime.h>
#include <cuda_bf16.h>
#include <cstddef>
#include <cstdint>

#define NN 10000
#define NE 320000
#define DD 256

// ---------------- scratch (device globals; no runtime allocation) ----------
__device__ float g_T[2 * NN * DD];      // edge-NN layer-1 output, per relation
__device__ float g_H[2 * NN * DD];      // edge-NN layer-2 output, per relation
__device__ float g_agg[NN * DD];        // scatter-sum result
__device__ float g_gates[NN * 4 * DD];  // LSTM gates (f columns unwritten)
__device__ float g_hn[NN * DD];         // LSTM output
__device__ float g_x1[NN * 128];
__device__ float g_x2[NN * 128];
__device__ float g_bcomb[4 * DD];       // b_ih + b_hh

// ---------------- tf32 helpers ---------------------------------------------
__device__ __forceinline__ float tf32r(float x)
{
    uint32_t u;
    asm("cvt.rna.tf32.f32 %0, %1;" : "=r"(u) : "f"(x));
    return __uint_as_float(u);
}

__device__ __forceinline__ void mma8(float* c, const uint32_t* a, const uint32_t* b)
{
    asm volatile(
        "mma.sync.aligned.m16n8k8.row.col.f32.tf32.tf32.f32 "
        "{%0,%1,%2,%3}, {%4,%5,%6,%7}, {%8,%9}, {%0,%1,%2,%3};"
        : "+f"(c[0]), "+f"(c[1]), "+f"(c[2]), "+f"(c[3])
        : "r"(a[0]), "r"(a[1]), "r"(a[2]), "r"(a[3]), "r"(b[0]), "r"(b[1]));
}

#define PITCH 36
#define TILE_F (128 * PITCH)
#define STAGE_F (4 * TILE_F)            // Ah, Al, Wh, Wl per stage
#define SMEM_BYTES (2 * STAGE_F * 4)    // 2 stages = 147456 B

// --------- 3xTF32 tensor-core GEMM: C = act(A @ W^T + bias) ----------------
// Error-compensated tf32 (hh + hl + lh); lo operands fed raw (HW truncates
// low 13 mantissa bits - second-order term, cutlass fast-3xtf32 trick).
// 128x128 block tile, BK=32, 512 threads = 16 warps (4m x 4n), warp 32x32.
// Double-buffered smem (2 stages), one __syncthreads per k-iter.
// blockIdx.z batches via strides. N%128==0, K%32==0; M guarded.
// SKIPF: remap column tiles 2..5 -> +256 (skip dead LSTM f-gate columns).
template <int ACT, int SKIPF>
__global__ void __launch_bounds__(512)
tgemm(const float* __restrict__ A, const float* __restrict__ W,
      const float* __restrict__ bias, float* __restrict__ C,
      int M, int N, int K,
      long sA, long sW, long sB, long sC)
{
    A    += (long)blockIdx.z * sA;
    W    += (long)blockIdx.z * sW;
    bias += (long)blockIdx.z * sB;
    C    += (long)blockIdx.z * sC;

    extern __shared__ float sm[];

    const int tid  = threadIdx.x;
    const int lane = tid & 31;
    const int wid  = tid >> 5;
    const int wm   = (wid & 3) * 32;     // 4 warp rows  x 32
    const int wn   = (wid >> 2) * 32;    // 4 warp cols  x 32

    const int m0 = blockIdx.y * 128;
    int n0 = blockIdx.x * 128;
    if (SKIPF && blockIdx.x >= 2) n0 += 256;

    // global tile loads: 512 threads, 2 x float4 per operand per k-slice
    const int lrow = tid >> 3;          // 0..63
    const int lcol = (tid & 7) * 4;     // 0..28

    float4 ra[2], rw[2];
#pragma unroll
    for (int i = 0; i < 2; i++) {
        int r  = lrow + i * 64;
        int gm = m0 + r;
        ra[i] = (gm < M) ? *(const float4*)(A + (size_t)gm * K + lcol)
                         : make_float4(0.f, 0.f, 0.f, 0.f);
        rw[i] = *(const float4*)(W + (size_t)(n0 + r) * K + lcol);
    }

    float acc[2][4][4];
#pragma unroll
    for (int mi = 0; mi < 2; mi++)
#pragma unroll
        for (int ni = 0; ni < 4; ni++)
#pragma unroll
            for (int q = 0; q < 4; q++) acc[mi][ni][q] = 0.f;

    // stash regs -> smem stage: hi via cvt.rna, lo as raw residual
    auto stash = [&](float* base) {
#pragma unroll
        for (int i = 0; i < 2; i++) {
            int off = (lrow + i * 64) * PITCH + lcol;
            float4 v = ra[i], h, l;
            h.x = tf32r(v.x); l.x = v.x - h.x;
            h.y = tf32r(v.y); l.y = v.y - h.y;
            h.z = tf32r(v.z); l.z = v.z - h.z;
            h.w = tf32r(v.w); l.w = v.w - h.w;
            *(float4*)&base[off]          = h;
            *(float4*)&base[TILE_F + off] = l;
            v = rw[i];
            h.x = tf32r(v.x); l.x = v.x - h.x;
            h.y = tf32r(v.y); l.y = v.y - h.y;
            h.z = tf32r(v.z); l.z = v.z - h.z;
            h.w = tf32r(v.w); l.w = v.w - h.w;
            *(float4*)&base[2 * TILE_F + off] = h;
            *(float4*)&base[3 * TILE_F + off] = l;
        }
    };

    stash(sm);                 // stage 0 holds k0 = 0
    __syncthreads();

    int stage = 0;
    for (int k0 = 0; k0 < K; k0 += 32) {
        int k1 = k0 + 32;
        if (k1 < K) {          // prefetch next k-slice into regs
#pragma unroll
            for (int i = 0; i < 2; i++) {
                int r  = lrow + i * 64;
                int gm = m0 + r;
                ra[i] = (gm < M) ? *(const float4*)(A + (size_t)gm * K + k1 + lcol)
                                 : make_float4(0.f, 0.f, 0.f, 0.f);
                rw[i] = *(const float4*)(W + (size_t)(n0 + r) * K + k1 + lcol);
            }
        }

        const float* Ah = sm + stage * STAGE_F;
        const float* Al = Ah + TILE_F;
        const float* Wh = Al + TILE_F;
        const float* Wl = Wh + TILE_F;

#pragma unroll
        for (int kk = 0; kk < 4; kk++) {
            const int kb = kk * 8;
            uint32_t ah[2][4], al[2][4], bh[4][2], bl[4][2];
#pragma unroll
            for (int mi = 0; mi < 2; mi++) {
                int r  = wm + mi * 16 + (lane >> 2);
                int o0 = r * PITCH + kb + (lane & 3);
                int o1 = o0 + 8 * PITCH;
                ah[mi][0] = __float_as_uint(Ah[o0]);
                ah[mi][1] = __float_as_uint(Ah[o1]);
                ah[mi][2] = __float_as_uint(Ah[o0 + 4]);
                ah[mi][3] = __float_as_uint(Ah[o1 + 4]);
                al[mi][0] = __float_as_uint(Al[o0]);
                al[mi][1] = __float_as_uint(Al[o1]);
                al[mi][2] = __float_as_uint(Al[o0 + 4]);
                al[mi][3] = __float_as_uint(Al[o1 + 4]);
            }
#pragma unroll
            for (int ni = 0; ni < 4; ni++) {
                int r = wn + ni * 8 + (lane >> 2);
                int o = r * PITCH + kb + (lane & 3);
                bh[ni][0] = __float_as_uint(Wh[o]);
                bh[ni][1] = __float_as_uint(Wh[o + 4]);
                bl[ni][0] = __float_as_uint(Wl[o]);
                bl[ni][1] = __float_as_uint(Wl[o + 4]);
            }
#pragma unroll
            for (int mi = 0; mi < 2; mi++)
#pragma unroll
                for (int ni = 0; ni < 4; ni++) {
                    mma8(acc[mi][ni], ah[mi], bh[ni]);
                    mma8(acc[mi][ni], ah[mi], bl[ni]);
                    mma8(acc[mi][ni], al[mi], bh[ni]);
                }
        }

        if (k1 < K) stash(sm + (stage ^ 1) * STAGE_F);
        __syncthreads();
        stage ^= 1;
    }

    // epilogue: bias + activation, float2 stores
#pragma unroll
    for (int mi = 0; mi < 2; mi++) {
        int row = m0 + wm + mi * 16 + (lane >> 2);
#pragma unroll
        for (int ni = 0; ni < 4; ni++) {
            int col = n0 + wn + ni * 8 + (lane & 3) * 2;
            float2 bv = *(const float2*)(bias + col);
            float2 o0, o1;
            o0.x = acc[mi][ni][0] + bv.x;
            o0.y = acc[mi][ni][1] + bv.y;
            o1.x = acc[mi][ni][2] + bv.x;
            o1.y = acc[mi][ni][3] + bv.y;
            if (ACT) {
                o0.x = fmaxf(o0.x, 0.f); o0.y = fmaxf(o0.y, 0.f);
                o1.x = fmaxf(o1.x, 0.f); o1.y = fmaxf(o1.y, 0.f);
            }
            if (row < M)     *(float2*)(C + (size_t)row * N + col)       = o0;
            if (row + 8 < M) *(float2*)(C + (size_t)(row + 8) * N + col) = o1;
        }
    }
}

// ---------------- small helpers --------------------------------------------
__global__ void zero_kernel(float4* __restrict__ p, int n4)
{
    int i = blockIdx.x * blockDim.x + threadIdx.x;
    if (i < n4) p[i] = make_float4(0.f, 0.f, 0.f, 0.f);
}

__global__ void bcomb_kernel(const float* __restrict__ a,
                             const float* __restrict__ b,
                             float* __restrict__ c)
{
    int i = threadIdx.x;  // 1024 threads
    c[i] = a[i] + b[i];
}

// ---------------- scatter: agg[dst[e]] += H[rel[e]][src[e]] ----------------
__global__ void __launch_bounds__(256)
scatter_kernel(const float* __restrict__ H, const int* __restrict__ src,
               const int* __restrict__ dst, const int* __restrict__ rel,
               float* __restrict__ agg)
{
    int e = blockIdx.x * 8 + (threadIdx.x >> 5);
    if (e >= NE) return;
    int lane = threadIdx.x & 31;
    int s = src[e], d = dst[e], r = rel[e];
    const float4* hrow = (const float4*)(H + ((size_t)r * NN + s) * DD);
    float* arow = agg + (size_t)d * DD;
#pragma unroll
    for (int t = 0; t < 2; t++) {
        int idx = lane + t * 32;
        float4 v = __ldg(&hrow[idx]);
        asm volatile("red.global.add.v4.f32 [%0], {%1, %2, %3, %4};"
                     :: "l"(arow + idx * 4),
                        "f"(v.x), "f"(v.y), "f"(v.z), "f"(v.w)
                     : "memory");
    }
}

// ---------------- LSTM elementwise (c0 = h0 = 0, f-gate dead) --------------
__global__ void lstm_kernel(const float* __restrict__ gates,
                            float* __restrict__ hn)
{
    int i = blockIdx.x * blockDim.x + threadIdx.x;
    if (i >= NN * DD) return;
    int n = i >> 8;
    int c = i & 255;
    const float* gr = gates + (size_t)n * (4 * DD);
    float ig = gr[c];
    float gg = gr[2 * DD + c];
    float og = gr[3 * DD + c];
    float si = 1.f / (1.f + expf(-ig));
    float cc = si * tanhf(gg);
    float so = 1.f / (1.f + expf(-og));
    hn[i] = so * tanhf(cc);
}

// ---------------- launcher --------------------------------------------------
extern "C" void kernel_launch(void* const* d_in, const int* in_sizes, int n_in,
                              void* d_out, int out_size)
{
    const float* feat  = (const float*)d_in[0];
    const int*   src   = (const int*)d_in[1];
    const int*   dst   = (const int*)d_in[2];
    const int*   rel   = (const int*)d_in[3];
    const float* W_rel = (const float*)d_in[4];
    const float* b_rel = (const float*)d_in[5];
    const float* W_ih  = (const float*)d_in[6];
    const float* b_ih  = (const float*)d_in[7];
    const float* b_hh  = (const float*)d_in[8];
    const float* W1    = (const float*)d_in[9];
    const float* b1    = (const float*)d_in[10];
    const float* W2    = (const float*)d_in[11];
    const float* b2    = (const float*)d_in[12];
    const float* W3    = (const float*)d_in[13];
    const float* b3    = (const float*)d_in[14];
    float* out = (float*)d_out;

    float *T, *H, *agg, *gates, *hn, *x1, *x2, *bc;
    cudaGetSymbolAddress((void**)&T,     g_T);
    cudaGetSymbolAddress((void**)&H,     g_H);
    cudaGetSymbolAddress((void**)&agg,   g_agg);
    cudaGetSymbolAddress((void**)&gates, g_gates);
    cudaGetSymbolAddress((void**)&hn,    g_hn);
    cudaGetSymbolAddress((void**)&x1,    g_x1);
    cudaGetSymbolAddress((void**)&x2,    g_x2);
    cudaGetSymbolAddress((void**)&bc,    g_bcomb);

    // allow 144KB dynamic smem (host-side state; no stream work enqueued)
    cudaFuncSetAttribute(tgemm<1, 0>,
        cudaFuncAttributeMaxDynamicSharedMemorySize, SMEM_BYTES);
    cudaFuncSetAttribute(tgemm<0, 1>,
        cudaFuncAttributeMaxDynamicSharedMemorySize, SMEM_BYTES);
    cudaFuncSetAttribute(tgemm<0, 0>,
        cudaFuncAttributeMaxDynamicSharedMemorySize, SMEM_BYTES);

    const int MB = (NN + 127) / 128;  // 79 row tiles
    const long ND = (long)NN * DD;

    // independent prep work first
    zero_kernel<<<(NN * DD / 4 + 255) / 256, 256>>>((float4*)agg, NN * DD / 4);
    bcomb_kernel<<<1, 1024>>>(b_ih, b_hh, bc);

    // edge-NN deduped to per-(node, relation), both relations via blockIdx.z
    tgemm<1, 0><<<dim3(DD / 128, MB, 2), 512, SMEM_BYTES>>>(
        feat, W_rel, b_rel, T, NN, DD, DD,
        0L, (long)DD * DD, (long)DD, ND);
    tgemm<1, 0><<<dim3(DD / 128, MB, 2), 512, SMEM_BYTES>>>(
        T, W_rel, b_rel, H, NN, DD, DD,
        ND, (long)DD * DD, (long)DD, ND);

    // scatter-sum into destination nodes
    scatter_kernel<<<NE / 8, 256>>>(H, src, dst, rel, agg);

    // LSTM gates GEMM: only i,g,o gate columns (f-gate dead, grid.x=6 remapped)
    tgemm<0, 1><<<dim3(6, MB, 1), 512, SMEM_BYTES>>>(
        agg, W_ih, bc, gates, NN, 4 * DD, DD, 0L, 0L, 0L, 0L);
    lstm_kernel<<<(NN * DD + 255) / 256, 256>>>(gates, hn);

    // global-update MLP
    tgemm<1, 0><<<dim3(1, MB, 1), 512, SMEM_BYTES>>>(hn, W1, b1, x1, NN, 128, DD,
                                                     0L, 0L, 0L, 0L);
    tgemm<1, 0><<<dim3(1, MB, 1), 512, SMEM_BYTES>>>(x1, W2, b2, x2, NN, 128, 128,
                                                     0L, 0L, 0L, 0L);
    tgemm<0, 0><<<dim3(DD / 128, MB, 1), 512, SMEM_BYTES>>>(x2, W3, b3, out,
                                                            NN, DD, 128,
                                                            0L, 0L, 0L, 0L);
}

// round 12
// speedup vs baseline: 1.3517x; 1.0714x over previous
#include <cuda_runtime.h>
#include <cuda_bf16.h>
#include <cstddef>
#include <cstdint>

#define NN 10000
#define NE 320000
#define DD 256

// ---------------- scratch (device globals; no runtime allocation) ----------
__device__ float g_T[2 * NN * DD];      // edge-NN layer-1 output, per relation
__device__ float g_H[2 * NN * DD];      // edge-NN layer-2 output, per relation
__device__ float g_agg[NN * DD];        // scatter-sum result
__device__ float g_gates[NN * 4 * DD];  // LSTM gates (f columns unwritten)
__device__ float g_hn[NN * DD];         // LSTM output
__device__ float g_x1[NN * 128];
__device__ float g_x2[NN * 128];
__device__ float g_bcomb[4 * DD];       // b_ih + b_hh

// ---------------- portable tensor-core helpers (NO a-suffix features) ------
__device__ __forceinline__ uint32_t smem_u32(const void* p)
{
    uint32_t a;
    asm("{ .reg .u64 t; cvta.to.shared.u64 t, %1; cvt.u32.u64 %0, t; }"
        : "=r"(a) : "l"(p));
    return a;
}

__device__ __forceinline__ void ldsm4(uint32_t* r, uint32_t addr)
{
    asm volatile("ldmatrix.sync.aligned.m8n8.x4.shared.b16 {%0,%1,%2,%3}, [%4];"
                 : "=r"(r[0]), "=r"(r[1]), "=r"(r[2]), "=r"(r[3]) : "r"(addr));
}

__device__ __forceinline__ void mma16(float* c, const uint32_t* a, const uint32_t* b)
{
    asm volatile(
        "mma.sync.aligned.m16n8k16.row.col.f32.bf16.bf16.f32 "
        "{%0,%1,%2,%3}, {%4,%5,%6,%7}, {%8,%9}, {%0,%1,%2,%3};"
        : "+f"(c[0]), "+f"(c[1]), "+f"(c[2]), "+f"(c[3])
        : "r"(a[0]), "r"(a[1]), "r"(a[2]), "r"(a[3]), "r"(b[0]), "r"(b[1]));
}

// ---------------- smem geometry ---------------------------------------------
// bf16 tile: 128 rows x 32 cols = 64 B/row = 8 KB. Per stage: A0 A1 A2 W0 W1 W2.
// Row layout: 4 chunks of 16B; swizzle chunk' = chunk ^ ((row>>1)&3) ->
// conflict-free for STS.128 stash and for 8-row ldmatrix fetches.
#define TILE_B  8192
#define STAGE_B (6 * TILE_B)
#define GSMEM   (2 * STAGE_B)           // 98304 B

// split 8 fp32 -> 3 x (8 bf16) by exact truncation; store 16B per level
__device__ __forceinline__ void pack3(const float4 v0, const float4 v1, char* p)
{
    const float vx[8] = {v0.x, v0.y, v0.z, v0.w, v1.x, v1.y, v1.z, v1.w};
    uint4 h, m, l;
    uint32_t* hp = (uint32_t*)&h;
    uint32_t* mp = (uint32_t*)&m;
    uint32_t* lp = (uint32_t*)&l;
#pragma unroll
    for (int j = 0; j < 4; j++) {
        float x0 = vx[2 * j], x1 = vx[2 * j + 1];
        uint32_t u0 = __float_as_uint(x0), u1 = __float_as_uint(x1);
        float r0 = x0 - __uint_as_float(u0 & 0xFFFF0000u);
        float r1 = x1 - __uint_as_float(u1 & 0xFFFF0000u);
        uint32_t w0 = __float_as_uint(r0), w1 = __float_as_uint(r1);
        float s0 = r0 - __uint_as_float(w0 & 0xFFFF0000u);
        float s1 = r1 - __uint_as_float(w1 & 0xFFFF0000u);
        hp[j] = __byte_perm(u0, u1, 0x7632);
        mp[j] = __byte_perm(w0, w1, 0x7632);
        lp[j] = __byte_perm(__float_as_uint(s0), __float_as_uint(s1), 0x7632);
    }
    *(uint4*)p                 = h;
    *(uint4*)(p + TILE_B)      = m;
    *(uint4*)(p + 2 * TILE_B)  = l;
}

// --------- bf16x6 tensor-core GEMM: C = act(A @ W^T + bias), ~fp32 accuracy
// A: [M,K] rm, W: [N,K] rm, bias: [N], C: [M,N] rm.
// 128x128 block, BK=32, 512 threads = 16 warps (4m x 4n), warp 32x32.
// 6 products (as+s<=2) of exact 3-term bf16 splits; double-buffered smem.
// blockIdx.z batches via strides. N%128==0, K%32==0; M guarded.
// SKIPF: remap column tiles >=2 -> +256 (skip dead LSTM f-gate columns).
template <int ACT, int SKIPF>
__global__ void __launch_bounds__(512)
tcgemm(const float* __restrict__ A, const float* __restrict__ W,
       const float* __restrict__ bias, float* __restrict__ C,
       int M, int N, int K,
       long sA, long sW, long sB, long sC)
{
    A    += (long)blockIdx.z * sA;
    W    += (long)blockIdx.z * sW;
    bias += (long)blockIdx.z * sB;
    C    += (long)blockIdx.z * sC;

    extern __shared__ char smc[];
    const uint32_t smb = smem_u32(smc);

    const int tid  = threadIdx.x;
    const int lane = tid & 31;
    const int wid  = tid >> 5;
    const int wm   = (wid & 3) * 32;
    const int wn   = (wid >> 2) * 32;

    const int m0 = blockIdx.y * 128;
    int n0 = blockIdx.x * 128;
    if (SKIPF && blockIdx.x >= 2) n0 += 256;

    // ---- stash mapping: thread -> (row 0..127, col group of 8) ----
    const int srow = tid >> 2;
    const int scol = (tid & 3) * 8;
    const uint32_t s_off = (uint32_t)(srow * 64 +
                           (((scol >> 3) ^ ((srow >> 1) & 3)) << 4));
    const int gm = m0 + srow;
    const float* Arow = A + (size_t)gm * K;
    const float* Wrow = W + (size_t)(n0 + srow) * K;
    const float4 fz = make_float4(0.f, 0.f, 0.f, 0.f);

    // ---- ldmatrix lane mapping (both operands NON-trans: smem rows are the
    // fragment's m/n axis, 16B chunks are the k axis) ----
    const int lr8  = lane & 7;
    const int rowA0 = wm + lr8 + ((lane >> 3) & 1) * 8;   // + mi*16
    const int rowB0 = wn + lr8 + (lane >> 4) * 8;         // + g*16
    const int akh  = lane >> 4;          // A k-half select
    const int bkh  = (lane >> 3) & 1;    // B k-half select
    const int aswz = (rowA0 >> 1) & 3;   // invariant under +16
    const int bswz = (rowB0 >> 1) & 3;

    float acc[2][4][4];
#pragma unroll
    for (int mi = 0; mi < 2; mi++)
#pragma unroll
        for (int ni = 0; ni < 4; ni++)
#pragma unroll
            for (int q = 0; q < 4; q++) acc[mi][ni][q] = 0.f;

    // ---- chunk-0 global loads ----
    float4 pa0, pa1, pw0, pw1;
    pa0 = (gm < M) ? *(const float4*)(Arow + scol)     : fz;
    pa1 = (gm < M) ? *(const float4*)(Arow + scol + 4) : fz;
    pw0 = *(const float4*)(Wrow + scol);
    pw1 = *(const float4*)(Wrow + scol + 4);

    auto stash = [&](int stg) {
        char* base = smc + stg * STAGE_B;
        pack3(pa0, pa1, base + s_off);
        pack3(pw0, pw1, base + 3 * TILE_B + s_off);
    };

    stash(0);
    __syncthreads();

    const int nc = K >> 5;
    int stage = 0;

    for (int c = 0; c < nc; c++) {
        // prefetch chunk c+1 (overlaps with MMA work below)
        if (c + 1 < nc) {
            int kb = (c + 1) << 5;
            pa0 = (gm < M) ? *(const float4*)(Arow + kb + scol)     : fz;
            pa1 = (gm < M) ? *(const float4*)(Arow + kb + scol + 4) : fz;
            pw0 = *(const float4*)(Wrow + kb + scol);
            pw1 = *(const float4*)(Wrow + kb + scol + 4);
        }

        const uint32_t stgb = smb + stage * STAGE_B;

#pragma unroll
        for (int ks = 0; ks < 2; ks++) {
            const int kc = ks * 2;
            uint32_t af[3][2][4];
#pragma unroll
            for (int s = 0; s < 3; s++)
#pragma unroll
                for (int mi = 0; mi < 2; mi++)
                    ldsm4(af[s][mi],
                          stgb + s * TILE_B + (rowA0 + mi * 16) * 64 +
                          (((kc + akh) ^ aswz) << 4));
#pragma unroll
            for (int s = 0; s < 3; s++) {
                uint32_t bf[2][4];
#pragma unroll
                for (int g = 0; g < 2; g++)
                    ldsm4(bf[g],
                          stgb + (3 + s) * TILE_B + (rowB0 + g * 16) * 64 +
                          (((kc + bkh) ^ bswz) << 4));
#pragma unroll
                for (int as = 0; as <= 2 - s; as++)
#pragma unroll
                    for (int mi = 0; mi < 2; mi++)
#pragma unroll
                        for (int ni = 0; ni < 4; ni++)
                            mma16(acc[mi][ni], af[as][mi],
                                  &bf[ni >> 1][(ni & 1) * 2]);
            }
        }

        if (c + 1 < nc) stash(stage ^ 1);
        __syncthreads();
        stage ^= 1;
    }

    // ---- epilogue: bias + activation, float2 stores ----
#pragma unroll
    for (int mi = 0; mi < 2; mi++) {
        int row = m0 + wm + mi * 16 + (lane >> 2);
#pragma unroll
        for (int ni = 0; ni < 4; ni++) {
            int col = n0 + wn + (ni >> 1) * 16 + (ni & 1) * 8 + (lane & 3) * 2;
            float2 bv = *(const float2*)(bias + col);
            float2 o0, o1;
            o0.x = acc[mi][ni][0] + bv.x;
            o0.y = acc[mi][ni][1] + bv.y;
            o1.x = acc[mi][ni][2] + bv.x;
            o1.y = acc[mi][ni][3] + bv.y;
            if (ACT) {
                o0.x = fmaxf(o0.x, 0.f); o0.y = fmaxf(o0.y, 0.f);
                o1.x = fmaxf(o1.x, 0.f); o1.y = fmaxf(o1.y, 0.f);
            }
            if (row < M)     *(float2*)(C + (size_t)row * N + col)       = o0;
            if (row + 8 < M) *(float2*)(C + (size_t)(row + 8) * N + col) = o1;
        }
    }
}

// ---------------- small helpers --------------------------------------------
__global__ void zero_kernel(float4* __restrict__ p, int n4)
{
    int i = blockIdx.x * blockDim.x + threadIdx.x;
    if (i < n4) p[i] = make_float4(0.f, 0.f, 0.f, 0.f);
}

__global__ void bcomb_kernel(const float* __restrict__ a,
                             const float* __restrict__ b,
                             float* __restrict__ c)
{
    int i = threadIdx.x;  // 1024 threads
    c[i] = a[i] + b[i];
}

// ---------------- scatter: agg[dst[e]] += H[rel[e]][src[e]] ----------------
__global__ void __launch_bounds__(256)
scatter_kernel(const float* __restrict__ H, const int* __restrict__ src,
               const int* __restrict__ dst, const int* __restrict__ rel,
               float* __restrict__ agg)
{
    int e = blockIdx.x * 8 + (threadIdx.x >> 5);
    if (e >= NE) return;
    int lane = threadIdx.x & 31;
    int s = src[e], d = dst[e], r = rel[e];
    const float4* hrow = (const float4*)(H + ((size_t)r * NN + s) * DD);
    float* arow = agg + (size_t)d * DD;
#pragma unroll
    for (int t = 0; t < 2; t++) {
        int idx = lane + t * 32;
        float4 v = __ldg(&hrow[idx]);
        asm volatile("red.global.add.v4.f32 [%0], {%1, %2, %3, %4};"
                     :: "l"(arow + idx * 4),
                        "f"(v.x), "f"(v.y), "f"(v.z), "f"(v.w)
                     : "memory");
    }
}

// ---------------- LSTM elementwise (c0 = h0 = 0, f-gate dead) --------------
__global__ void lstm_kernel(const float* __restrict__ gates,
                            float* __restrict__ hn)
{
    int i = blockIdx.x * blockDim.x + threadIdx.x;
    if (i >= NN * DD) return;
    int n = i >> 8;
    int c = i & 255;
    const float* gr = gates + (size_t)n * (4 * DD);
    float ig = gr[c];
    float gg = gr[2 * DD + c];
    float og = gr[3 * DD + c];
    float si = 1.f / (1.f + expf(-ig));
    float cc = si * tanhf(gg);
    float so = 1.f / (1.f + expf(-og));
    hn[i] = so * tanhf(cc);
}

// ---------------- launcher --------------------------------------------------
extern "C" void kernel_launch(void* const* d_in, const int* in_sizes, int n_in,
                              void* d_out, int out_size)
{
    const float* feat  = (const float*)d_in[0];
    const int*   src   = (const int*)d_in[1];
    const int*   dst   = (const int*)d_in[2];
    const int*   rel   = (const int*)d_in[3];
    const float* W_rel = (const float*)d_in[4];
    const float* b_rel = (const float*)d_in[5];
    const float* W_ih  = (const float*)d_in[6];
    const float* b_ih  = (const float*)d_in[7];
    const float* b_hh  = (const float*)d_in[8];
    const float* W1    = (const float*)d_in[9];
    const float* b1    = (const float*)d_in[10];
    const float* W2    = (const float*)d_in[11];
    const float* b2    = (const float*)d_in[12];
    const float* W3    = (const float*)d_in[13];
    const float* b3    = (const float*)d_in[14];
    float* out = (float*)d_out;

    float *T, *H, *agg, *gates, *hn, *x1, *x2, *bc;
    cudaGetSymbolAddress((void**)&T,     g_T);
    cudaGetSymbolAddress((void**)&H,     g_H);
    cudaGetSymbolAddress((void**)&agg,   g_agg);
    cudaGetSymbolAddress((void**)&gates, g_gates);
    cudaGetSymbolAddress((void**)&hn,    g_hn);
    cudaGetSymbolAddress((void**)&x1,    g_x1);
    cudaGetSymbolAddress((void**)&x2,    g_x2);
    cudaGetSymbolAddress((void**)&bc,    g_bcomb);

    // allow 96KB dynamic smem (host-side state; no stream work enqueued)
    cudaFuncSetAttribute(tcgemm<1, 0>,
        cudaFuncAttributeMaxDynamicSharedMemorySize, GSMEM);
    cudaFuncSetAttribute(tcgemm<0, 1>,
        cudaFuncAttributeMaxDynamicSharedMemorySize, GSMEM);
    cudaFuncSetAttribute(tcgemm<0, 0>,
        cudaFuncAttributeMaxDynamicSharedMemorySize, GSMEM);

    const int MB = (NN + 127) / 128;  // 79 row tiles
    const long ND = (long)NN * DD;

    // independent prep work first
    zero_kernel<<<(NN * DD / 4 + 255) / 256, 256>>>((float4*)agg, NN * DD / 4);
    bcomb_kernel<<<1, 1024>>>(b_ih, b_hh, bc);

    // edge-NN deduped to per-(node, relation), both relations via blockIdx.z
    tcgemm<1, 0><<<dim3(2, MB, 2), 512, GSMEM>>>(
        feat, W_rel, b_rel, T, NN, DD, DD,
        0L, (long)DD * DD, (long)DD, ND);
    tcgemm<1, 0><<<dim3(2, MB, 2), 512, GSMEM>>>(
        T, W_rel, b_rel, H, NN, DD, DD,
        ND, (long)DD * DD, (long)DD, ND);

    // scatter-sum into destination nodes
    scatter_kernel<<<NE / 8, 256>>>(H, src, dst, rel, agg);

    // LSTM gates GEMM: only i,g,o gate columns (f-gate dead, grid.x=6 remapped)
    tcgemm<0, 1><<<dim3(6, MB, 1), 512, GSMEM>>>(
        agg, W_ih, bc, gates, NN, 4 * DD, DD, 0L, 0L, 0L, 0L);
    lstm_kernel<<<(NN * DD + 255) / 256, 256>>>(gates, hn);

    // global-update MLP
    tcgemm<1, 0><<<dim3(1, MB, 1), 512, GSMEM>>>(hn, W1, b1, x1, NN, 128, DD,
                                                 0L, 0L, 0L, 0L);
    tcgemm<1, 0><<<dim3(1, MB, 1), 512, GSMEM>>>(x1, W2, b2, x2, NN, 128, 128,
                                                 0L, 0L, 0L, 0L);
    tcgemm<0, 0><<<dim3(2, MB, 1), 512, GSMEM>>>(x2, W3, b3, out, NN, DD, 128,
                                                 0L, 0L, 0L, 0L);
}